// round 13
// baseline (speedup 1.0000x reference)
#include <cuda_runtime.h>

// Temporal-blocked persistent solver, R13: occupancy-1 / max-ILP variant.
//  - NT=256, ONE block per SM (__launch_bounds__(256,1) -> 255-reg budget),
//    GRID=148, stride=ceil(N/148)=7085, PPT=29 -> LBUF=7424, TILE=7168.
//  - Rationale: R6 showed more TLP doesn't help; R8/R10 showed the occ-2
//    128-reg cap prevents interleaving the 15+ independent ~40-cycle
//    lg2->fma->ex2 MUFU chains. Occ 1 doubles the register budget so ptxas
//    can software-pipeline ~29 chains per thread (ILP replaces TLP).
//  - C1-scaled conservative state: R=rho, Ms=C1*mom; derived Vs=C1*v,
//    FPs=C1^2*(rho v^2+P); C1^2 folded into the pow constant.
//  - Static-parity double buffering (time loop unrolled x2), float4 edges,
//    ONE __syncthreads per step.  [all carried from R8, the best config]
//  - No clamps in hot loop; halo garbage advances 1 cell/step, never reaches
//    the stored interior.

#define NT   256
#define PPT  29
#define LBUF (NT * PPT)            // 7424
#define HALO 128
#define TILE (LBUF - 2 * HALO)     // 7168
#define GRID 148

__device__ __forceinline__ float xlg2(float x) {
    float r; asm("lg2.approx.f32 %0, %1;" : "=f"(r) : "f"(x)); return r;
}
__device__ __forceinline__ float xex2(float x) {
    float r; asm("ex2.approx.f32 %0, %1;" : "=f"(r) : "f"(x)); return r;
}
__device__ __forceinline__ float xrcp(float x) {
    float r; asm("rcp.approx.f32 %0, %1;" : "=f"(r) : "f"(x)); return r;
}

// One LxF step; SL/SF are compile-time-selected edge buffers.
__device__ __forceinline__ void lxf_step(float R[PPT], float Ms[PPT],
                                         float4* __restrict__ SL,
                                         float4* __restrict__ SF,
                                         int t, int lt, int rt)
{
    const float LGC12 = -15.287712379549449f;   // lg2(C1^2), C1 = DT/(2*DX)
    float Vs[PPT], FPs[PPT];

    // pass 1: Vs = C1*v, FPs = C1^2*(rho v^2 + P)  (29 independent chains)
    #pragma unroll
    for (int j = 0; j < PPT; ++j) {
        float rinv = xrcp(R[j]);
        Vs[j] = Ms[j] * rinv;
        float Pp = xex2(fmaf(1.4f, xlg2(R[j]), LGC12));
        FPs[j] = fmaf(Ms[j], Vs[j], Pp);
    }

    // edge publish: one float4 per end
    SL[t] = make_float4(R[PPT - 1], Ms[PPT - 1], Vs[PPT - 1], FPs[PPT - 1]);
    SF[t] = make_float4(R[0],       Ms[0],       Vs[0],       FPs[0]);
    __syncthreads();

    float4 eL = SL[lt];   // neighbor's last cell  (my cell -1)
    float4 eR = SF[rt];   // neighbor's first cell (my cell +PPT)

    // pass 2: update on scaled (R, Ms); prev values of Vs/FPs read from the
    // (never-overwritten) arrays, only R/Ms need the 2-register carry.
    float pR = eL.x, pM = eL.y;
    #pragma unroll
    for (int j = 0; j < PPT; ++j) {
        const bool last = (j == PPT - 1);           // compile-time
        float nR = last ? eR.x : R[j + 1];
        float nM = last ? eR.y : Ms[j + 1];
        float nV = last ? eR.z : Vs[j + 1];
        float nF = last ? eR.w : FPs[j + 1];
        float pV = (j == 0) ? eL.z : Vs[j - 1];
        float pF = (j == 0) ? eL.w : FPs[j - 1];

        float rnew  = fmaf(0.5f, nR + pR, pM - nM);
        float visc  = fmaf(-2.0f, Vs[j], nV + pV);  // C1*(vn+vp-2v)
        float m0    = fmaf(0.5f, nM + pM, pF - nF);
        float msnew = fmaf(0.01f * R[j], visc, m0); // C2 = DT*MU/DX^2

        pR = R[j]; pM = Ms[j];
        R[j] = rnew; Ms[j] = msnew;
    }
}

__global__ __launch_bounds__(NT, 1)
void obf_solver_kernel(const float* __restrict__ rho0,
                       const float* __restrict__ v0,
                       const int*   __restrict__ n_steps_ptr,
                       float*       __restrict__ out,
                       int N, int stride)
{
    // Two statically-selected edge buffers: [0]=Last-cell, [1]=First-cell.
    __shared__ float4 S0[2][NT];
    __shared__ float4 S1[2][NT];

    const int t = threadIdx.x;
    const int b = blockIdx.x;
    const int base = b * stride - HALO + t * PPT;

    const float C1    = 0.005f;
    const float INVC1 = 200.0f;

    float R[PPT], Ms[PPT];

    // ---- load initial state (periodic wrap); Ms = C1 * rho * v ----
    #pragma unroll
    for (int j = 0; j < PPT; ++j) {
        int g = base + j + N;
        if (g >= N) g -= N;
        if (g >= N) g -= N;
        float r = rho0[g];
        float v = v0[g];
        R[j]  = r;
        Ms[j] = (C1 * r) * v;
    }

    const int n_steps = *n_steps_ptr;

    const int lt = (t == 0)      ? 0      : t - 1;
    const int rt = (t == NT - 1) ? NT - 1 : t + 1;

    int s = 0;
    for (; s + 1 < n_steps; s += 2) {
        lxf_step(R, Ms, S0[0], S0[1], t, lt, rt);   // parity 0
        lxf_step(R, Ms, S1[0], S1[1], t, lt, rt);   // parity 1
    }
    if (s < n_steps) {
        lxf_step(R, Ms, S0[0], S0[1], t, lt, rt);
    }

    // ---- store valid interior: rho and v = (Ms/C1)/max(rho,1e-10) ----
    float* orho = out;
    float* ov   = out + N;
    #pragma unroll
    for (int j = 0; j < PPT; ++j) {
        int l = t * PPT + j;                 // local index in [0, LBUF)
        if (l >= HALO && l < LBUF - HALO) {
            int g = b * stride + (l - HALO);
            if (g >= N) g -= N;
            orho[g] = R[j];
            ov[g]   = (INVC1 * Ms[j]) * xrcp(fmaxf(R[j], 1e-10f));
        }
    }
}

extern "C" void kernel_launch(void* const* d_in, const int* in_sizes, int n_in,
                              void* d_out, int out_size)
{
    const float* rho0   = (const float*)d_in[0];
    const float* v0     = (const float*)d_in[1];
    const int*   nsteps = (const int*)d_in[2];
    float*       out    = (float*)d_out;

    const int N = in_sizes[0];
    int grid = GRID;
    if ((long long)grid * TILE < N)                 // safety for other shapes
        grid = (N + TILE - 1) / TILE;
    int stride = (N + grid - 1) / grid;             // 7085 <= TILE here

    obf_solver_kernel<<<grid, NT>>>(rho0, v0, nsteps, out, N, stride);
}

// round 14
// speedup vs baseline: 1.0805x; 1.0805x over previous
#include <cuda_runtime.h>

// Temporal-blocked persistent solver, R14: SSA-style double-buffered state.
//  - R8 config (the empirical best): NT=256, PPT=15, LBUF=3840, HALO=128,
//    TILE=3584, GRID=296, stride=3543, occ 2, one __syncthreads per step,
//    static-parity float4 edge buffers.
//  - KEY CHANGE vs R8: pass 2 writes NEW state into separate register arrays
//    (R,Ms -> Rb,Mb), alternating direction each parity of the x2-unrolled
//    time loop. All neighbor reads are direct compile-time-indexed array
//    reads (Ro[j-1], Vs[j+1], ...) -> no loop-carried register copies ->
//    eliminates the ~10 MOV/cell ptxas was emitting for the rotation.
//  - C1-scaled conservative state: R=rho, Ms=C1*mom; Vs=C1*v,
//    FPs=C1^2*(rho v^2+P); C1^2 folded into the pow constant.
//  - No clamps in hot loop; halo garbage advances 1 cell/step, never reaches
//    the stored interior.

#define NT   256
#define PPT  15
#define LBUF (NT * PPT)            // 3840
#define HALO 128
#define TILE (LBUF - 2 * HALO)     // 3584
#define GRID 296

__device__ __forceinline__ float xlg2(float x) {
    float r; asm("lg2.approx.f32 %0, %1;" : "=f"(r) : "f"(x)); return r;
}
__device__ __forceinline__ float xex2(float x) {
    float r; asm("ex2.approx.f32 %0, %1;" : "=f"(r) : "f"(x)); return r;
}
__device__ __forceinline__ float xrcp(float x) {
    float r; asm("rcp.approx.f32 %0, %1;" : "=f"(r) : "f"(x)); return r;
}

// One LxF step, old state (Ro,Mo) -> new state (Rn,Mn).
// SL/SF are compile-time-selected edge buffers (static parity).
__device__ __forceinline__ void lxf_step(const float Ro[PPT], const float Mo[PPT],
                                         float Rn[PPT], float Mn[PPT],
                                         float4* __restrict__ SL,
                                         float4* __restrict__ SF,
                                         int t, int lt, int rt)
{
    const float LGC12 = -15.287712379549449f;   // lg2(C1^2), C1 = DT/(2*DX)
    float Vs[PPT], FPs[PPT];

    // pass 1: Vs = C1*v, FPs = C1^2*(rho v^2 + P)
    #pragma unroll
    for (int j = 0; j < PPT; ++j) {
        float rinv = xrcp(Ro[j]);
        Vs[j] = Mo[j] * rinv;
        float Pp = xex2(fmaf(1.4f, xlg2(Ro[j]), LGC12));
        FPs[j] = fmaf(Mo[j], Vs[j], Pp);
    }

    // edge publish: one float4 per end
    SL[t] = make_float4(Ro[PPT - 1], Mo[PPT - 1], Vs[PPT - 1], FPs[PPT - 1]);
    SF[t] = make_float4(Ro[0],       Mo[0],       Vs[0],       FPs[0]);
    __syncthreads();

    float4 eL = SL[lt];   // neighbor's last cell  (my cell -1)
    float4 eR = SF[rt];   // neighbor's first cell (my cell +PPT)

    // pass 2: pure SSA — every operand is a direct array read or edge value.
    #pragma unroll
    for (int j = 0; j < PPT; ++j) {
        float pR = (j == 0) ? eL.x : Ro[j - 1];
        float pM = (j == 0) ? eL.y : Mo[j - 1];
        float pV = (j == 0) ? eL.z : Vs[j - 1];
        float pF = (j == 0) ? eL.w : FPs[j - 1];
        float nR = (j == PPT - 1) ? eR.x : Ro[j + 1];
        float nM = (j == PPT - 1) ? eR.y : Mo[j + 1];
        float nV = (j == PPT - 1) ? eR.z : Vs[j + 1];
        float nF = (j == PPT - 1) ? eR.w : FPs[j + 1];

        float rnew = fmaf(0.5f, nR + pR, pM - nM);
        float visc = fmaf(-2.0f, Vs[j], nV + pV);            // C1*(vn+vp-2v)
        float m0   = fmaf(0.5f, nM + pM, pF - nF);
        Rn[j] = rnew;
        Mn[j] = fmaf(0.01f * Ro[j], visc, m0);               // C2 = DT*MU/DX^2
    }
}

__global__ __launch_bounds__(NT, 2)
void obf_solver_kernel(const float* __restrict__ rho0,
                       const float* __restrict__ v0,
                       const int*   __restrict__ n_steps_ptr,
                       float*       __restrict__ out,
                       int N, int stride)
{
    // Two statically-selected edge buffers: [0]=Last-cell, [1]=First-cell.
    __shared__ float4 S0[2][NT];
    __shared__ float4 S1[2][NT];

    const int t = threadIdx.x;
    const int b = blockIdx.x;
    const int base = b * stride - HALO + t * PPT;

    const float C1    = 0.005f;
    const float INVC1 = 200.0f;

    float R[PPT], Ms[PPT];       // state buffer A
    float Rb[PPT], Mb[PPT];      // state buffer B

    // ---- load initial state (periodic wrap); Ms = C1 * rho * v ----
    #pragma unroll
    for (int j = 0; j < PPT; ++j) {
        int g = base + j + N;
        if (g >= N) g -= N;
        if (g >= N) g -= N;
        float r = rho0[g];
        float v = v0[g];
        R[j]  = r;
        Ms[j] = (C1 * r) * v;
    }

    const int n_steps = *n_steps_ptr;

    const int lt = (t == 0)      ? 0      : t - 1;
    const int rt = (t == NT - 1) ? NT - 1 : t + 1;

    int s = 0;
    for (; s + 1 < n_steps; s += 2) {
        lxf_step(R,  Ms, Rb, Mb, S0[0], S0[1], t, lt, rt);   // A -> B, parity 0
        lxf_step(Rb, Mb, R,  Ms, S1[0], S1[1], t, lt, rt);   // B -> A, parity 1
    }
    if (s < n_steps) {                                       // odd n_steps tail
        lxf_step(R, Ms, Rb, Mb, S0[0], S0[1], t, lt, rt);
        #pragma unroll
        for (int j = 0; j < PPT; ++j) { R[j] = Rb[j]; Ms[j] = Mb[j]; }
    }

    // ---- store valid interior: rho and v = (Ms/C1)/max(rho,1e-10) ----
    float* orho = out;
    float* ov   = out + N;
    #pragma unroll
    for (int j = 0; j < PPT; ++j) {
        int l = t * PPT + j;                 // local index in [0, LBUF)
        if (l >= HALO && l < LBUF - HALO) {
            int g = b * stride + (l - HALO);
            if (g >= N) g -= N;
            orho[g] = R[j];
            ov[g]   = (INVC1 * Ms[j]) * xrcp(fmaxf(R[j], 1e-10f));
        }
    }
}

extern "C" void kernel_launch(void* const* d_in, const int* in_sizes, int n_in,
                              void* d_out, int out_size)
{
    const float* rho0   = (const float*)d_in[0];
    const float* v0     = (const float*)d_in[1];
    const int*   nsteps = (const int*)d_in[2];
    float*       out    = (float*)d_out;

    const int N = in_sizes[0];
    int grid = GRID;
    if ((long long)grid * TILE < N)                 // safety for other shapes
        grid = (N + TILE - 1) / TILE;
    int stride = (N + grid - 1) / grid;             // 3543 <= TILE here

    obf_solver_kernel<<<grid, NT>>>(rho0, v0, nsteps, out, N, stride);
}